// round 6
// baseline (speedup 1.0000x reference)
#include <cuda_runtime.h>
#include <cstdint>

// Batched GEMM out[b,n,m] = sum_e A[b,n,e]*B[b,m,e]; b=8, n=m=2048, e=1024, fp32.
// sm_103 base target (no tcgen05 available through this toolchain) ->
// mma.sync.m16n8k8 tf32 with fp32 accumulators, cvt.rna tf32 conversion on load.

#define THREADS 512
#define BM 128            // n-rows per CTA
#define BN 256            // m-cols per CTA
#define BK 32             // k floats per stage
#define E_DIM 1024
#define SEQ 2048
#define NSTAGE (E_DIM / BK)     // 32

#define ROWB 144                 // padded smem row stride (bytes): conflict-free + affine
#define A_BYTES (BM * ROWB)      // 18432
#define B_BYTES (BN * ROWB)      // 36864
#define STAGE_BYTES (A_BYTES + B_BYTES)   // 55296
#define SMEM_TOTAL (2 * STAGE_BYTES)      // 110592

__device__ __forceinline__ uint32_t smem_u32(const void* p) {
    uint32_t a;
    asm("{ .reg .u64 t; cvta.to.shared.u64 t, %1; cvt.u32.u64 %0, t; }" : "=r"(a) : "l"(p));
    return a;
}

__device__ __forceinline__ uint32_t f2tf32(float f) {
    uint32_t r;
    asm("cvt.rna.tf32.f32 %0, %1;" : "=r"(r) : "f"(f));
    return r;
}

__device__ __forceinline__ void sts128(uint32_t a, uint32_t r0, uint32_t r1,
                                       uint32_t r2, uint32_t r3) {
    asm volatile("st.shared.v4.b32 [%0], {%1,%2,%3,%4};"
                 :: "r"(a), "r"(r0), "r"(r1), "r"(r2), "r"(r3) : "memory");
}

__device__ __forceinline__ uint32_t lds32(uint32_t a) {
    uint32_t v;
    asm volatile("ld.shared.b32 %0, [%1];" : "=r"(v) : "r"(a));
    return v;
}

__device__ __forceinline__ void mma_tf32(float c[4], uint32_t a0, uint32_t a1,
                                         uint32_t a2, uint32_t a3,
                                         uint32_t b0, uint32_t b1) {
    asm volatile(
        "mma.sync.aligned.m16n8k8.row.col.f32.tf32.tf32.f32 "
        "{%0,%1,%2,%3}, {%4,%5,%6,%7}, {%8,%9}, {%0,%1,%2,%3};"
        : "+f"(c[0]), "+f"(c[1]), "+f"(c[2]), "+f"(c[3])
        : "r"(a0), "r"(a1), "r"(a2), "r"(a3), "r"(b0), "r"(b1));
}

extern "C" __global__ void __launch_bounds__(THREADS)
attn_matrix_mma_kernel(const float* __restrict__ A0,
                       const float* __restrict__ B0,
                       float* __restrict__ out) {
    extern __shared__ char smem[];
    const uint32_t sbase = smem_u32(smem);
    const int tid  = threadIdx.x;
    const int wid  = tid >> 5;
    const int lane = tid & 31;
    const int g    = lane >> 2;   // group id (0..7)
    const int tig  = lane & 3;    // thread-in-group (0..3)
    const int wn   = wid >> 2;    // warp n-row group (0..3), 32 rows each
    const int wm   = wid & 3;     // warp m-col group (0..3), 64 cols each

    const int mtile = blockIdx.x;          // over m (BN)
    const int ntile = blockIdx.y;          // over n (BM)
    const int b     = blockIdx.z;
    const long nbase = (long)ntile * BM;
    const long mbase = (long)mtile * BN;
    const float* Ap = A0 + ((long)b * SEQ + nbase) * E_DIM;
    const float* Bp = B0 + ((long)b * SEQ + mbase) * E_DIM;

    // global-load lanes: 512 threads, each handles (row = tid>>3, 16B chunk q = tid&7)
    const int lrow = tid >> 3;             // 0..63
    const int lq   = tid & 7;
    const float* gA = Ap + (long)lrow * E_DIM + lq * 4;
    const float* gB = Bp + (long)lrow * E_DIM + lq * 4;

    // STS bases (stage 0); rows padded to 144B
    const uint32_t stsA = sbase + (uint32_t)(lrow * ROWB + lq * 16);
    const uint32_t stsB = stsA + A_BYTES;

    // fragment LDS bases (stage 0)
    const uint32_t ldsA0 = sbase + (uint32_t)((wn * 32 + g) * ROWB + tig * 4);
    const uint32_t ldsB0 = sbase + A_BYTES + (uint32_t)((wm * 64 + g) * ROWB + tig * 4);

    float acc[2][8][4];
    #pragma unroll
    for (int i = 0; i < 2; i++)
        #pragma unroll
        for (int j = 0; j < 8; j++)
            #pragma unroll
            for (int k = 0; k < 4; k++) acc[i][j][k] = 0.f;

    // ---- prologue: fill stage 0 ----
    {
        #pragma unroll
        for (int t = 0; t < 2; t++) {
            float4 v = *(const float4*)(gA + (long)t * 64 * E_DIM);
            sts128(stsA + (uint32_t)(t * 64 * ROWB),
                   f2tf32(v.x), f2tf32(v.y), f2tf32(v.z), f2tf32(v.w));
        }
        #pragma unroll
        for (int t = 0; t < 4; t++) {
            float4 v = *(const float4*)(gB + (long)t * 64 * E_DIM);
            sts128(stsB + (uint32_t)(t * 64 * ROWB),
                   f2tf32(v.x), f2tf32(v.y), f2tf32(v.z), f2tf32(v.w));
        }
    }
    __syncthreads();

    // ---- main loop ----
    for (int ks = 0; ks < NSTAGE; ks++) {
        const int buf = ks & 1;
        const uint32_t aB = ldsA0 + (uint32_t)(buf * STAGE_BYTES);
        const uint32_t bB = ldsB0 + (uint32_t)(buf * STAGE_BYTES);

        // prefetch next stage into registers (hides L2/DRAM latency under mma)
        float4 pfA[2], pfB[4];
        const bool pf = (ks + 1 < NSTAGE);
        if (pf) {
            const float* ga = gA + (ks + 1) * BK;
            const float* gb = gB + (ks + 1) * BK;
            #pragma unroll
            for (int t = 0; t < 2; t++) pfA[t] = *(const float4*)(ga + (long)t * 64 * E_DIM);
            #pragma unroll
            for (int t = 0; t < 4; t++) pfB[t] = *(const float4*)(gb + (long)t * 64 * E_DIM);
        }

        #pragma unroll
        for (int kk = 0; kk < 4; kk++) {
            uint32_t a[2][4], bb[8][2];
            #pragma unroll
            for (int mi = 0; mi < 2; mi++) {
                a[mi][0] = lds32(aB + (uint32_t)(mi * 16 * ROWB + kk * 32));
                a[mi][1] = lds32(aB + (uint32_t)(mi * 16 * ROWB + 8 * ROWB + kk * 32));
                a[mi][2] = lds32(aB + (uint32_t)(mi * 16 * ROWB + kk * 32 + 16));
                a[mi][3] = lds32(aB + (uint32_t)(mi * 16 * ROWB + 8 * ROWB + kk * 32 + 16));
            }
            #pragma unroll
            for (int ni = 0; ni < 8; ni++) {
                bb[ni][0] = lds32(bB + (uint32_t)(ni * 8 * ROWB + kk * 32));
                bb[ni][1] = lds32(bB + (uint32_t)(ni * 8 * ROWB + kk * 32 + 16));
            }
            #pragma unroll
            for (int mi = 0; mi < 2; mi++)
                #pragma unroll
                for (int ni = 0; ni < 8; ni++)
                    mma_tf32(acc[mi][ni], a[mi][0], a[mi][1], a[mi][2], a[mi][3],
                             bb[ni][0], bb[ni][1]);
        }

        if (pf) {
            const uint32_t nb = (uint32_t)((buf ^ 1) * STAGE_BYTES);
            #pragma unroll
            for (int t = 0; t < 2; t++)
                sts128(stsA + nb + (uint32_t)(t * 64 * ROWB),
                       f2tf32(pfA[t].x), f2tf32(pfA[t].y), f2tf32(pfA[t].z), f2tf32(pfA[t].w));
            #pragma unroll
            for (int t = 0; t < 4; t++)
                sts128(stsB + nb + (uint32_t)(t * 64 * ROWB),
                       f2tf32(pfB[t].x), f2tf32(pfB[t].y), f2tf32(pfB[t].z), f2tf32(pfB[t].w));
        }
        __syncthreads();
    }

    // ---- epilogue ----
    const int orow = (int)nbase + wn * 32 + g;
    const int ocol = (int)mbase + wm * 64 + tig * 2;
    float* ob = out + (long)b * SEQ * SEQ;
    #pragma unroll
    for (int mi = 0; mi < 2; mi++) {
        #pragma unroll
        for (int ni = 0; ni < 8; ni++) {
            const long r0 = (long)(orow + mi * 16) * SEQ;
            float2 v0 = make_float2(acc[mi][ni][0], acc[mi][ni][1]);
            float2 v1 = make_float2(acc[mi][ni][2], acc[mi][ni][3]);
            *(float2*)(ob + r0 + ocol + ni * 8) = v0;
            *(float2*)(ob + r0 + 8 * SEQ + ocol + ni * 8) = v1;
        }
    }
}

extern "C" void kernel_launch(void* const* d_in, const int* in_sizes, int n_in,
                              void* d_out, int out_size) {
    const float* a = (const float*)d_in[0];   // mat_0 [8, 2048, 1024]
    const float* b = (const float*)d_in[1];   // mat_1 [8, 2048, 1024]
    float* o = (float*)d_out;                 // out   [8, 2048, 2048]

    cudaFuncSetAttribute(attn_matrix_mma_kernel,
                         cudaFuncAttributeMaxDynamicSharedMemorySize, SMEM_TOTAL);
    dim3 grid(SEQ / BN, SEQ / BM, 8);         // (8, 16, 8) = 1024 CTAs
    attn_matrix_mma_kernel<<<grid, THREADS, SMEM_TOTAL>>>(a, b, o);
}